// round 13
// baseline (speedup 1.0000x reference)
#include <cuda_runtime.h>
#include <cstdint>
#include <math.h>

// ---------------- constants ----------------
#define PH 514
#define PW 514
#define NIMG 16                // 2 sets (pred,tgt) * 8 batch
#define NPIX (NIMG*512*512)    // 4,194,304 tight pixels
#define SLOTS_PER_IMG (PH*PW)  // 264196
#define NSLOT (8*SLOTS_PER_IMG)
#define TOTSLOT (2*NSLOT)      // 4,227,136
#define DMAX 16384
#define PI_D 3.141592653589793
#define ANG_EPS 1e-4f          // fp32 prefilter margin (fp32 angle err ~1e-6)

// CC fused-iteration tiling
#define TW 128
#define HALO 16
#define SW 160                 // TW + 2*HALO
#define NG 40                  // SW/4 int4 groups
#define SSTRIDE 164            // padded row stride (ints)
#define NSTRIP 23
#define ROWS_PER 7             // 23*7 = 161 >= 158
#define CC_TPB 1024
#define CC_SMEM (2*SW*SSTRIDE*4)   // 209,920 B
#define NTILE 256              // 16 images * 4x4 tiles

// ---------------- static device scratch ----------------
__device__ __align__(16) int g_lab0[NPIX];
__device__ __align__(16) int g_lab1[NPIX];   // ping-pong; later reused as slot cache
__device__ int g_d0[NTILE];
__device__ int g_d1[NTILE];
__device__ int g_cnt [TOTSLOT];
__device__ int g_sumR[TOTSLOT];
__device__ int g_sumC[TOTSLOT];
__device__ double g_cent[TOTSLOT][2];        // per-slot centroid (cr, cc)
__device__ unsigned int g_min32[TOTSLOT];    // fp32 monotone angle-key min
__device__ unsigned long long g_minKey[TOTSLOT];
__device__ unsigned int      g_minRC [TOTSLOT];
__device__ double g_desc[NIMG][DMAX][4];
__device__ int g_M[NIMG];
__device__ int g_valid[NIMG];

// ---------------- init ----------------
__global__ void k_init()
{
    long long i = (long long)blockIdx.x * blockDim.x + threadIdx.x;
    long long stride = (long long)gridDim.x * blockDim.x;
    for (long long j = i; j < TOTSLOT; j += stride) {
        g_cnt[j] = 0; g_sumR[j] = 0; g_sumC[j] = 0;
        g_minKey[j] = ~0ull; g_minRC[j] = ~0u; g_min32[j] = ~0u;
    }
    if (i < NTILE) g_d0[i] = 1;
    if (i < NIMG) { g_M[i] = 0; g_valid[i] = 0; }
}

// ---------------- fill initial labels (tight layout, padded-index values) ----------------
__global__ void k_fill(const float* __restrict__ pred, const float* __restrict__ tgt)
{
    int i = blockIdx.x * blockDim.x + threadIdx.x;
    if (i >= NPIX) return;
    int sb = i >> 18; int set = sb >> 3, b = sb & 7;
    int rc = i & 262143;
    const float* src = (set == 0 ? pred : tgt) + ((long long)b << 18);
    float v = src[rc];
    bool m = (set == 0) ? (v > 0.0f) : (v == 1.0f);
    int r = rc >> 9, c = rc & 511;
    g_lab0[i] = m ? ((b * PH + r + 1) * PW + (c + 1)) : 0;
}

// ---------------- fused CC: software-pipelined row processing ----------------
struct RawRow { int4 m; int l, r; };

// stage A: issue the smem loads only (no dependent math)
__device__ __forceinline__ RawRow raw_row(const int* src, int r, int g, bool needL, bool needR)
{
    const int* p = src + r * SSTRIDE + (g << 2);
    RawRow x;
    x.m = *(const int4*)p;
    x.l = needL ? p[-1] : 0;
    x.r = needR ? p[4]  : 0;
    return x;
}

// stage B: shuffles + horizontal 3-max (consumes a RawRow loaded one step earlier)
__device__ __forceinline__ int4 hm_row(const RawRow& x, int g, int lane)
{
    int l  = __shfl_up_sync(0xffffffffu, x.m.w, 1);
    int rr = __shfl_down_sync(0xffffffffu, x.m.x, 1);
    if (lane == 0)  l  = x.l;
    if (lane == 31) rr = x.r;
    if (g == 0)      l  = 0;
    if (g == NG - 1) rr = 0;
    int4 h;
    h.x = max(l,     max(x.m.x, x.m.y));
    h.y = max(x.m.x, max(x.m.y, x.m.z));
    h.z = max(x.m.y, max(x.m.z, x.m.w));
    h.w = max(x.m.z, max(x.m.w, rr));
    return h;
}

__global__ __launch_bounds__(CC_TPB, 1)
void k_cc(int flip, int iters)
{
    extern __shared__ int smem[];
    int* SA = smem;
    int* SB = smem + SW * SSTRIDE;
    __shared__ int s_active, s_changed;

    const int* gin = flip ? g_lab1 : g_lab0;
    int*       gout = flip ? g_lab0 : g_lab1;
    const int* din = flip ? g_d1 : g_d0;
    int*       dout = flip ? g_d0 : g_d1;

    int sb = blockIdx.z, ty = blockIdx.y, tx = blockIdx.x;
    int tile = (sb << 4) | (ty << 2) | tx;
    int t = threadIdx.x;

    if (t == 0) {
        int a = 0;
        for (int dy = -1; dy <= 1; dy++)
            for (int dx = -1; dx <= 1; dx++) {
                int ny = ty + dy, nx = tx + dx;
                if (ny >= 0 && ny < 4 && nx >= 0 && nx < 4)
                    a |= din[(sb << 4) | (ny << 2) | nx];
            }
        s_active = a; s_changed = 0;
    }
    __syncthreads();

    long long base = (long long)sb << 18;
    int gr0 = ty * TW - HALO, gc0 = tx * TW - HALO;

    if (!s_active) {
        for (int idx = t; idx < 128 * 32; idx += CC_TPB) {
            int row = idx >> 5, grp = idx & 31;
            long long gi = base + (long long)(((ty * TW + row) << 9) + tx * TW + (grp << 2));
            *(int4*)(gout + gi) = *(const int4*)(gin + gi);
        }
        if (t == 0) dout[tile] = 0;
        return;
    }

    // load 160x160 tile (zeros outside image)
    for (int idx = t; idx < SW * NG; idx += CC_TPB) {
        int row = idx / NG, grp = idx % NG;
        int gr = gr0 + row, gc = gc0 + (grp << 2);
        int4 v;
        if (gr >= 0 && gr < 512 && gc >= 0 && gc + 3 < 512) {
            v = *(const int4*)(gin + base + ((long long)gr << 9) + gc);
        } else {
            v = make_int4(0, 0, 0, 0);
            if (gr >= 0 && gr < 512) {
                long long rb = base + ((long long)gr << 9);
                if (gc >= 0     && gc < 512)     v.x = gin[rb + gc];
                if (gc + 1 >= 0 && gc + 1 < 512) v.y = gin[rb + gc + 1];
                if (gc + 2 >= 0 && gc + 2 < 512) v.z = gin[rb + gc + 2];
                if (gc + 3 >= 0 && gc + 3 < 512) v.w = gin[rb + gc + 3];
            }
        }
        *(int4*)(SA + row * SSTRIDE + (grp << 2)) = v;
    }
    __syncthreads();

    int g = t % NG, s = t / NG;
    int lane = t & 31;
    int lo0 = 1 + s * ROWS_PER;                       // first output row of strip
    int hi0 = min(lo0 + ROWS_PER, SW - 1);            // exclusive; idle strips: hi0<=lo0
    bool needL = (lane == 0)  && (g > 0);
    bool needR = (lane == 31) && (g < NG - 1);
    // clamped prologue row indices (idle strips must stay inside smem)
    int rP  = max(min(lo0 - 1, SW - 1), 0);
    int rc_ = min(lo0,     SW - 1);
    int rN1 = min(lo0 + 1, SW - 1);

    for (int it = 0; it < iters; it++) {
        const int* src = (it & 1) ? SB : SA;
        int*       dst = (it & 1) ? SA : SB;
        // shrinking trapezoid, warp-granular skip only (out-of-region writes are
        // deterministic from the src double-buffer and never read later)
        int rem = iters - it;
        int rmin = HALO - rem + 1;
        int rmax = SW - HALO + rem - 1;
        int lo = max(lo0, rmin), hi = min(hi0, rmax);
        unsigned anyb = __ballot_sync(0xffffffffu, lo < hi);
        if (anyb != 0) {
            // 2-deep pipeline: LDS of row r+2 issued one full step before its
            // shuffles+maxes; shfl->consume gap softened by the independent
            // max(hmA,hmB) precombine.
            RawRow rA = raw_row(src, rP,  g, needL, needR);
            RawRow rB = raw_row(src, rc_, g, needL, needR);
            int4 hmA = hm_row(rA, g, lane);                 // row lo-1
            RawRow rC = raw_row(src, rN1, g, needL, needR);
            int4 hmB = hm_row(rB, g, lane);                 // row lo
            int4 mB = rB.m;                                 // m of output row
            #pragma unroll
            for (int k = 0; k < ROWS_PER; k++) {
                int r = lo0 + k;
                RawRow rD = raw_row(src, min(r + 2, SW - 1), g, needL, needR);
                int4 hmC = hm_row(rC, g, lane);             // row r+1 (LDS from prev step)
                if (r < hi0) {
                    int4 pm;                                 // independent of this step's shfl
                    pm.x = max(hmA.x, hmB.x);
                    pm.y = max(hmA.y, hmB.y);
                    pm.z = max(hmA.z, hmB.z);
                    pm.w = max(hmA.w, hmB.w);
                    int4 o;
                    o.x = (mB.x > 0) ? max(pm.x, hmC.x) : 0;
                    o.y = (mB.y > 0) ? max(pm.y, hmC.y) : 0;
                    o.z = (mB.z > 0) ? max(pm.z, hmC.z) : 0;
                    o.w = (mB.w > 0) ? max(pm.w, hmC.w) : 0;
                    *(int4*)(dst + r * SSTRIDE + (g << 2)) = o;
                }
                mB = rC.m; rC = rD; hmA = hmB; hmB = hmC;
            }
        }
        __syncthreads();
    }

    // iters is always even -> result in SA; write interior + change detection
    for (int idx = t; idx < 128 * 32; idx += CC_TPB) {
        int row = idx >> 5, grp = idx & 31;
        long long gi = base + (long long)(((ty * TW + row) << 9) + tx * TW + (grp << 2));
        int4 v = *(const int4*)(SA + (row + HALO) * SSTRIDE + ((grp + 4) << 2));
        int4 old = *(const int4*)(gin + gi);
        if ((v.x != old.x) | (v.y != old.y) | (v.z != old.z) | (v.w != old.w)) s_changed = 1;
        *(int4*)(gout + gi) = v;
    }
    __syncthreads();
    if (t == 0) dout[tile] = s_changed;
}

// ---------------- helpers (tight layout) ----------------
__device__ __forceinline__ int lab_at(const int* G, long long base, int r, int c)
{
    return (r >= 0 && r < 512 && c >= 0 && c < 512) ? G[base + (r << 9) + c] : 0;
}

__device__ __forceinline__ void pix_label(int sb, int r, int c, int& L, bool& isb)
{
    long long base = (long long)sb << 18;
    L = g_lab0[base + (r << 9) + c];
    isb = false;
    if (L > 0) {
        bool allfg = (lab_at(g_lab0, base, r - 1, c - 1) > 0)
                   & (lab_at(g_lab0, base, r - 1, c    ) > 0)
                   & (lab_at(g_lab0, base, r - 1, c + 1) > 0)
                   & (lab_at(g_lab0, base, r,     c - 1) > 0)
                   & (lab_at(g_lab0, base, r,     c + 1) > 0)
                   & (lab_at(g_lab0, base, r + 1, c - 1) > 0)
                   & (lab_at(g_lab0, base, r + 1, c    ) > 0)
                   & (lab_at(g_lab0, base, r + 1, c + 1) > 0);
        isb = !allfg;
    }
}

// exact fp64 monotone angle key (ordering identical to numpy argsort of atan2)
__device__ __forceinline__ unsigned long long angle_key(double y, double x)
{
    double ang = atan2(y, x);
    long long bits = __double_as_longlong(ang);
    unsigned long long u = (unsigned long long)bits;
    return (bits < 0) ? ~u : (u | 0x8000000000000000ull);
}

// fp32 monotone angle key (prefilter only)
__device__ __forceinline__ unsigned int key32_of(float ang)
{
    int bits = __float_as_int(ang);
    unsigned u = (unsigned)bits;
    return (bits < 0) ? ~u : (u | 0x80000000u);
}

__device__ __forceinline__ float ang_of_key32(unsigned k)
{
    return (k & 0x80000000u) ? __int_as_float((int)(k & 0x7fffffffu))
                             : __int_as_float((int)~k);
}

// ---------------- pass B: counts + sums; cache slot id in g_lab1 ----------------
__global__ void k_stats()
{
    int sb = blockIdx.z; int set = sb >> 3, b = sb & 7;
    int c = blockIdx.x * 32 + threadIdx.x;
    int r = blockIdx.y * 8  + threadIdx.y;
    int L; bool isb;
    pix_label(sb, r, c, L, isb);
    int zs = set * NSLOT + b * SLOTS_PER_IMG;
    int gs = isb ? (set * NSLOT + L) : zs;
    g_lab1[(sb << 18) | (r << 9) | c] = gs;

    unsigned zc = isb ? 0u : 1u;
    unsigned zr = isb ? 0u : (unsigned)r;
    unsigned zl = isb ? 0u : (unsigned)c;
    for (int o = 16; o > 0; o >>= 1) {
        zc += __shfl_down_sync(0xffffffffu, zc, o);
        zr += __shfl_down_sync(0xffffffffu, zr, o);
        zl += __shfl_down_sync(0xffffffffu, zl, o);
    }
    __shared__ unsigned sc[8], sr[8], sl[8];
    int wid = threadIdx.y, lane = threadIdx.x;
    if (lane == 0) { sc[wid] = zc; sr[wid] = zr; sl[wid] = zl; }
    __syncthreads();
    if (lane == 0 && wid == 0) {
        unsigned tc = 0, tr = 0, tl = 0;
        for (int i = 0; i < 8; i++) { tc += sc[i]; tr += sr[i]; tl += sl[i]; }
        if (tc) {
            atomicAdd(&g_cnt[zs],  (int)tc);
            atomicAdd(&g_sumR[zs], (int)tr);
            atomicAdd(&g_sumC[zs], (int)tl);
        }
    }
    if (isb) {
        atomicAdd(&g_cnt[gs], 1);
        atomicAdd(&g_sumR[gs], r);
        atomicAdd(&g_sumC[gs], c);
    }
}

// ---------------- centroid precompute (removes all per-pixel fp64 divides) ----------------
__global__ void k_cent()
{
    long long i = (long long)blockIdx.x * blockDim.x + threadIdx.x;
    long long stride = (long long)gridDim.x * blockDim.x;
    for (long long j = i; j < TOTSLOT; j += stride) {
        int n = g_cnt[j];
        if (n > 0) {
            g_cent[j][0] = (double)g_sumR[j] / (double)n;
            g_cent[j][1] = (double)g_sumC[j] / (double)n;
        }
    }
}

// ---------------- pass A: fp32 prefilter min angle per slot ----------------
__global__ void k_angA()
{
    int sb = blockIdx.z; int set = sb >> 3, b = sb & 7;
    int c = blockIdx.x * 32 + threadIdx.x;
    int r = blockIdx.y * 8  + threadIdx.y;
    int i = (sb << 18) | (r << 9) | c;
    int gs = g_lab1[i];
    int zs = set * NSLOT + b * SLOTS_PER_IMG;
    bool isb = (gs != zs);

    double cr = g_cent[gs][0], cc = g_cent[gs][1];
    float ang = atan2f((float)((double)c - cc), (float)((double)r - cr));
    unsigned key = key32_of(ang);

    if (isb) atomicMin(&g_min32[gs], key);

    unsigned zkey = isb ? ~0u : key;
    for (int o = 16; o > 0; o >>= 1) {
        unsigned v = __shfl_down_sync(0xffffffffu, zkey, o);
        zkey = min(zkey, v);
    }
    __shared__ unsigned sk[8];
    int wid = threadIdx.y, lane = threadIdx.x;
    if (lane == 0) sk[wid] = zkey;
    __syncthreads();
    if (lane == 0 && wid == 0) {
        unsigned mk = sk[0];
        for (int i2 = 1; i2 < 8; i2++) mk = min(mk, sk[i2]);
        if (mk != ~0u) atomicMin(&g_min32[zs], mk);
    }
}

// ---------------- pass B: exact fp64 min among fp32-filtered candidates ----------------
__global__ void k_angB()
{
    int sb = blockIdx.z; int set = sb >> 3, b = sb & 7;
    int c = blockIdx.x * 32 + threadIdx.x;
    int r = blockIdx.y * 8  + threadIdx.y;
    int i = (sb << 18) | (r << 9) | c;
    int gs = g_lab1[i];

    double cr = g_cent[gs][0], cc = g_cent[gs][1];
    double dy = (double)c - cc, dx = (double)r - cr;
    float ang = atan2f((float)dy, (float)dx);
    float amin = ang_of_key32(g_min32[gs]);
    if (ang <= amin + ANG_EPS) {
        unsigned long long key = angle_key(dy, dx);
        atomicMin(&g_minKey[gs], key);
    }
}

// ---------------- pass C: raster tie-break among exact-min pixels ----------------
__global__ void k_angC()
{
    int sb = blockIdx.z; int set = sb >> 3, b = sb & 7;
    int c = blockIdx.x * 32 + threadIdx.x;
    int r = blockIdx.y * 8  + threadIdx.y;
    int i = (sb << 18) | (r << 9) | c;
    int gs = g_lab1[i];

    double cr = g_cent[gs][0], cc = g_cent[gs][1];
    double dy = (double)c - cc, dx = (double)r - cr;
    float ang = atan2f((float)dy, (float)dx);
    float amin = ang_of_key32(g_min32[gs]);
    if (ang <= amin + ANG_EPS) {
        unsigned long long key = angle_key(dy, dx);
        if (key == g_minKey[gs]) {
            unsigned rc = ((unsigned)r << 9) | (unsigned)c;
            atomicMin(&g_minRC[gs], rc);
        }
    }
}

// ---------------- finalize: ordered compaction ----------------
__global__ void k_final()
{
    int sb = blockIdx.x; int set = sb >> 3, b = sb & 7;
    int base = set * NSLOT + b * SLOTS_PER_IMG;
    const int CH = (SLOTS_PER_IMG + 1023) / 1024;
    int t = threadIdx.x;
    int lo = t * CH, hi = min(lo + CH, SLOTS_PER_IMG);

    int act = 0, kept = 0;
    for (int l = lo; l < hi; l++) {
        int n = g_cnt[base + l];
        if (n > 0) { act++; if (n >= 10) kept++; }
    }
    __shared__ int sKept[1024];
    __shared__ int offs[1025];
    __shared__ int sAct[1024];
    __shared__ int totAct;
    sAct[t] = act; sKept[t] = kept;
    __syncthreads();
    if (t == 0) {
        int s = 0, a = 0;
        for (int i = 0; i < 1024; i++) { offs[i] = s; s += sKept[i]; a += sAct[i]; }
        offs[1024] = s; totAct = a;
    }
    __syncthreads();

    int pos = offs[t];
    for (int l = lo; l < hi; l++) {
        int n = g_cnt[base + l];
        if (n >= 10) {
            if (pos < DMAX) {
                unsigned rc = g_minRC[base + l];
                double r0 = (double)(rc >> 9), c0 = (double)(rc & 511u);
                double Ab = sqrt(r0 * r0 + c0 * c0);
                g_desc[sb][pos][0] = (double)g_sumR[base + l] / (double)n;
                g_desc[sb][pos][1] = (double)g_sumC[base + l] / (double)n;
                g_desc[sb][pos][2] = Ab / PI_D;
                g_desc[sb][pos][3] = Ab / (2.0 * PI_D);
            }
            pos++;
        }
    }
    if (t == 0) {
        int tot = offs[1024]; if (tot > DMAX) tot = DMAX;
        g_M[sb] = tot;
        g_valid[sb] = (totAct > 1) && (tot > 0);
    }
}

// ---------------- matching + output ----------------
__global__ void k_match(const float* __restrict__ wptr, float* __restrict__ out)
{
    __shared__ double red[256];
    __shared__ double Stot;
    int t = threadIdx.x;
    if (t == 0) Stot = 0.0;
    __syncthreads();

    for (int b = 0; b < 8; b++) {
        double local = 0.0;
        if (g_valid[b] && g_valid[8 + b]) {
            int Mp = g_M[b], Mt = g_M[8 + b];
            const double (*P)[4] = g_desc[b];
            const double (*T)[4] = g_desc[8 + b];
            if (Mt <= Mp) {
                for (int i = t; i < Mt; i += 256) {
                    double tx = T[i][0], ty = T[i][1];
                    int m = 0; double bd = 1e300;
                    for (int j = 0; j < Mp; j++) {
                        double dx = tx - P[j][0], dy = ty - P[j][1];
                        double d = dx * dx + dy * dy;
                        if (d < bd) { bd = d; m = j; }
                    }
                    local += fabs(P[m][2] - T[i][2]) + fabs(P[m][3] - T[i][3]);
                }
            } else {
                for (int i = t; i < Mp; i += 256) {
                    double px = P[i][0], py = P[i][1];
                    int m = 0; double bd = 1e300;
                    for (int j = 0; j < Mt; j++) {
                        double dx = px - T[j][0], dy = py - T[j][1];
                        double d = dx * dx + dy * dy;
                        if (d < bd) { bd = d; m = j; }
                    }
                    local += fabs(T[m][2] - P[i][2]) + fabs(T[m][3] - P[i][3]);
                }
            }
        }
        red[t] = local; __syncthreads();
        for (int s = 128; s > 0; s >>= 1) { if (t < s) red[t] += red[t + s]; __syncthreads(); }
        if (t == 0) Stot += red[0];
        __syncthreads();
    }
    if (t == 0) {
        float w = *wptr;
        out[0] = (float)Stot * (0.5f * w * w);
    }
}

// ---------------- launch ----------------
extern "C" void kernel_launch(void* const* d_in, const int* in_sizes, int n_in,
                              void* d_out, int out_size)
{
    (void)in_sizes; (void)n_in; (void)out_size;
    const float* pred = (const float*)d_in[0];
    const float* tgt  = (const float*)d_in[1];
    const float* w    = (const float*)d_in[2];
    float* out = (float*)d_out;

    static bool attr_set = false;
    if (!attr_set) {
        cudaFuncSetAttribute(k_cc, cudaFuncAttributeMaxDynamicSharedMemorySize, CC_SMEM);
        attr_set = true;
    }

    k_init<<<4096, 256>>>();
    k_fill<<<NPIX / 256, 256>>>(pred, tgt);

    // 500 iterations = 31 launches of 16 + 1 launch of 4 (both even)
    for (int k = 0; k < 32; k++) {
        int iters = (k == 31) ? 4 : 16;
        k_cc<<<dim3(4, 4, 16), CC_TPB, CC_SMEM>>>(k & 1, iters);
    }
    // 32 launches (even) -> final labels in g_lab0

    dim3 bl(32, 8);
    k_stats<<<dim3(16, 64, 16), bl>>>();
    k_cent <<<4096, 256>>>();
    k_angA <<<dim3(16, 64, 16), bl>>>();
    k_angB <<<dim3(16, 64, 16), bl>>>();
    k_angC <<<dim3(16, 64, 16), bl>>>();
    k_final<<<16, 1024>>>();
    k_match<<<1, 256>>>(w, out);
}

// round 14
// speedup vs baseline: 1.0768x; 1.0768x over previous
#include <cuda_runtime.h>
#include <cstdint>
#include <math.h>

// ---------------- constants ----------------
#define PH 514
#define PW 514
#define NIMG 16                // 2 sets (pred,tgt) * 8 batch
#define NPIX (NIMG*512*512)    // 4,194,304 tight pixels
#define SLOTS_PER_IMG (PH*PW)  // 264196
#define NSLOT (8*SLOTS_PER_IMG)
#define TOTSLOT (2*NSLOT)      // 4,227,136
#define DMAX 16384
#define PI_D 3.141592653589793
#define ANG_EPS 1e-4f          // fp32 prefilter margin (fp32 angle err ~1e-6)

// CC fused-iteration tiling
#define TW 128
#define HALO 16
#define SW 160                 // TW + 2*HALO
#define NG 40                  // SW/4 int4 groups
#define SSTRIDE 164            // padded row stride (ints)
#define NSTRIP 23
#define ROWS_PER 7             // 23*7 = 161 >= 158
#define CC_TPB 1024
#define CC_SMEM (2*SW*SSTRIDE*4)   // 209,920 B
#define NTILE 256              // 16 images * 4x4 tiles

// ---------------- static device scratch ----------------
__device__ __align__(16) int g_lab0[NPIX];
__device__ __align__(16) int g_lab1[NPIX];   // ping-pong; later reused as slot cache
__device__ int g_d0[NTILE];
__device__ int g_d1[NTILE];
__device__ int g_cnt [TOTSLOT];
__device__ int g_sumR[TOTSLOT];
__device__ int g_sumC[TOTSLOT];
__device__ double g_cent[TOTSLOT][2];        // per-slot centroid (cr, cc)
__device__ unsigned int g_min32[TOTSLOT];    // fp32 monotone angle-key min
__device__ unsigned long long g_minKey[TOTSLOT];
__device__ unsigned int      g_minRC [TOTSLOT];
__device__ double g_desc[NIMG][DMAX][4];
__device__ int g_M[NIMG];
__device__ int g_valid[NIMG];

// ---------------- init (minKey/minRC/min32 are lazily initialized in k_cent) ----------------
__global__ void k_init()
{
    long long i = (long long)blockIdx.x * blockDim.x + threadIdx.x;
    long long stride = (long long)gridDim.x * blockDim.x;
    for (long long j = i; j < TOTSLOT; j += stride) {
        g_cnt[j] = 0; g_sumR[j] = 0; g_sumC[j] = 0;
    }
    if (i < NTILE) g_d0[i] = 1;
    if (i < NIMG) { g_M[i] = 0; g_valid[i] = 0; }
}

// ---------------- fill initial labels (tight layout, padded-index values) ----------------
__global__ void k_fill(const float* __restrict__ pred, const float* __restrict__ tgt)
{
    int i = blockIdx.x * blockDim.x + threadIdx.x;
    if (i >= NPIX) return;
    int sb = i >> 18; int set = sb >> 3, b = sb & 7;
    int rc = i & 262143;
    const float* src = (set == 0 ? pred : tgt) + ((long long)b << 18);
    float v = src[rc];
    bool m = (set == 0) ? (v > 0.0f) : (v == 1.0f);
    int r = rc >> 9, c = rc & 511;
    g_lab0[i] = m ? ((b * PH + r + 1) * PW + (c + 1)) : 0;
}

// ---------------- fused CC iterations (R8 form — local optimum, do not touch) ----------------
__device__ __forceinline__ int4 hmrow_s(const int* src, int r, int g, int lane, int4& m)
{
    const int* p = src + r * SSTRIDE + (g << 2);
    m = *(const int4*)p;
    int l  = __shfl_up_sync(0xffffffffu, m.w, 1);
    int rr = __shfl_down_sync(0xffffffffu, m.x, 1);
    if (lane == 0  && g > 0)      l  = p[-1];
    if (lane == 31 && g < NG - 1) rr = p[4];
    if (g == 0)      l  = 0;
    if (g == NG - 1) rr = 0;
    int4 h;
    h.x = max(l,   max(m.x, m.y));
    h.y = max(m.x, max(m.y, m.z));
    h.z = max(m.y, max(m.z, m.w));
    h.w = max(m.z, max(m.w, rr));
    return h;
}

__global__ __launch_bounds__(CC_TPB, 1)
void k_cc(int flip, int iters)
{
    extern __shared__ int smem[];
    int* SA = smem;
    int* SB = smem + SW * SSTRIDE;
    __shared__ int s_active, s_changed;

    const int* gin = flip ? g_lab1 : g_lab0;
    int*       gout = flip ? g_lab0 : g_lab1;
    const int* din = flip ? g_d1 : g_d0;
    int*       dout = flip ? g_d0 : g_d1;

    int sb = blockIdx.z, ty = blockIdx.y, tx = blockIdx.x;
    int tile = (sb << 4) | (ty << 2) | tx;
    int t = threadIdx.x;

    if (t == 0) {
        int a = 0;
        for (int dy = -1; dy <= 1; dy++)
            for (int dx = -1; dx <= 1; dx++) {
                int ny = ty + dy, nx = tx + dx;
                if (ny >= 0 && ny < 4 && nx >= 0 && nx < 4)
                    a |= din[(sb << 4) | (ny << 2) | nx];
            }
        s_active = a; s_changed = 0;
    }
    __syncthreads();

    long long base = (long long)sb << 18;
    int gr0 = ty * TW - HALO, gc0 = tx * TW - HALO;

    if (!s_active) {
        for (int idx = t; idx < 128 * 32; idx += CC_TPB) {
            int row = idx >> 5, grp = idx & 31;
            long long gi = base + (long long)(((ty * TW + row) << 9) + tx * TW + (grp << 2));
            *(int4*)(gout + gi) = *(const int4*)(gin + gi);
        }
        if (t == 0) dout[tile] = 0;
        return;
    }

    for (int idx = t; idx < SW * NG; idx += CC_TPB) {
        int row = idx / NG, grp = idx % NG;
        int gr = gr0 + row, gc = gc0 + (grp << 2);
        int4 v;
        if (gr >= 0 && gr < 512 && gc >= 0 && gc + 3 < 512) {
            v = *(const int4*)(gin + base + ((long long)gr << 9) + gc);
        } else {
            v = make_int4(0, 0, 0, 0);
            if (gr >= 0 && gr < 512) {
                long long rb = base + ((long long)gr << 9);
                if (gc >= 0     && gc < 512)     v.x = gin[rb + gc];
                if (gc + 1 >= 0 && gc + 1 < 512) v.y = gin[rb + gc + 1];
                if (gc + 2 >= 0 && gc + 2 < 512) v.z = gin[rb + gc + 2];
                if (gc + 3 >= 0 && gc + 3 < 512) v.w = gin[rb + gc + 3];
            }
        }
        *(int4*)(SA + row * SSTRIDE + (grp << 2)) = v;
    }
    __syncthreads();

    int g = t % NG, s = t / NG;
    int lane = t & 31;
    int lo0 = 1 + s * ROWS_PER;
    int hi0 = min(lo0 + ROWS_PER, SW - 1);

    for (int it = 0; it < iters; it++) {
        const int* src = (it & 1) ? SB : SA;
        int*       dst = (it & 1) ? SA : SB;
        int rem = iters - it;
        int rmin = HALO - rem + 1;
        int rmax = SW - HALO + rem - 1;
        int lo = max(lo0, rmin), hi = min(hi0, rmax);
        unsigned anyb = __ballot_sync(0xffffffffu, lo < hi);
        if (anyb != 0) {
            int rp = min(lo0 - 1, SW - 1);
            int rc_ = min(lo0,     SW - 1);
            int4 mtmp;
            int4 hm_prev = hmrow_s(src, rp, g, lane, mtmp);
            int4 m_cur;
            int4 hm_cur  = hmrow_s(src, rc_, g, lane, m_cur);
            #pragma unroll
            for (int k = 0; k < ROWS_PER; k++) {
                int r = lo0 + k;
                int rn = min(r + 1, SW - 1);
                int4 m_next;
                int4 hm_next = hmrow_s(src, rn, g, lane, m_next);
                if (r < hi0) {
                    int4 o;
                    o.x = (m_cur.x > 0) ? max(hm_prev.x, max(hm_cur.x, hm_next.x)) : 0;
                    o.y = (m_cur.y > 0) ? max(hm_prev.y, max(hm_cur.y, hm_next.y)) : 0;
                    o.z = (m_cur.z > 0) ? max(hm_prev.z, max(hm_cur.z, hm_next.z)) : 0;
                    o.w = (m_cur.w > 0) ? max(hm_prev.w, max(hm_cur.w, hm_next.w)) : 0;
                    *(int4*)(dst + r * SSTRIDE + (g << 2)) = o;
                }
                hm_prev = hm_cur; hm_cur = hm_next; m_cur = m_next;
            }
        }
        __syncthreads();
    }

    for (int idx = t; idx < 128 * 32; idx += CC_TPB) {
        int row = idx >> 5, grp = idx & 31;
        long long gi = base + (long long)(((ty * TW + row) << 9) + tx * TW + (grp << 2));
        int4 v = *(const int4*)(SA + (row + HALO) * SSTRIDE + ((grp + 4) << 2));
        int4 old = *(const int4*)(gin + gi);
        if ((v.x != old.x) | (v.y != old.y) | (v.z != old.z) | (v.w != old.w)) s_changed = 1;
        *(int4*)(gout + gi) = v;
    }
    __syncthreads();
    if (t == 0) dout[tile] = s_changed;
}

// ---------------- helpers ----------------
// exact fp64 monotone angle key (ordering identical to numpy argsort of atan2)
__device__ __forceinline__ unsigned long long angle_key(double y, double x)
{
    double ang = atan2(y, x);
    long long bits = __double_as_longlong(ang);
    unsigned long long u = (unsigned long long)bits;
    return (bits < 0) ? ~u : (u | 0x8000000000000000ull);
}

// fp32 monotone angle key (prefilter only)
__device__ __forceinline__ unsigned int key32_of(float ang)
{
    int bits = __float_as_int(ang);
    unsigned u = (unsigned)bits;
    return (bits < 0) ? ~u : (u | 0x80000000u);
}

__device__ __forceinline__ float ang_of_key32(unsigned k)
{
    return (k & 0x80000000u) ? __int_as_float((int)(k & 0x7fffffffu))
                             : __int_as_float((int)~k);
}

// ---------------- pass B: counts + sums (4 px/thread, vectorized); cache slot ids ----------------
__global__ void k_stats()
{
    int sb = blockIdx.z; int set = sb >> 3, b = sb & 7;
    int tx = threadIdx.x;                        // 0..31
    int c0 = (blockIdx.x * 32 + tx) << 2;        // 0,4,...,508
    int r  = blockIdx.y * 8 + threadIdx.y;       // 0..511
    long long base = (long long)sb << 18;

    // load 3 rows x (int4 + left/right scalars), zero outside image
    int4 mU = make_int4(0,0,0,0), mM, mD = make_int4(0,0,0,0);
    int lU = 0, rU = 0, lM = 0, rM = 0, lD = 0, rD = 0;
    bool hasL = (c0 > 0), hasR = (c0 + 4 < 512);
    {
        long long rb = base + ((long long)r << 9);
        mM = *(const int4*)(g_lab0 + rb + c0);
        if (hasL) lM = g_lab0[rb + c0 - 1];
        if (hasR) rM = g_lab0[rb + c0 + 4];
        if (r > 0) {
            long long ru = rb - 512;
            mU = *(const int4*)(g_lab0 + ru + c0);
            if (hasL) lU = g_lab0[ru + c0 - 1];
            if (hasR) rU = g_lab0[ru + c0 + 4];
        }
        if (r < 511) {
            long long rd = rb + 512;
            mD = *(const int4*)(g_lab0 + rd + c0);
            if (hasL) lD = g_lab0[rd + c0 - 1];
            if (hasR) rD = g_lab0[rd + c0 + 4];
        }
    }
    int U[6] = { lU, mU.x, mU.y, mU.z, mU.w, rU };
    int M[6] = { lM, mM.x, mM.y, mM.z, mM.w, rM };
    int D[6] = { lD, mD.x, mD.y, mD.z, mD.w, rD };

    int zs = set * NSLOT + b * SLOTS_PER_IMG;
    int L[4]; bool isb[4]; int gsv[4];
    #pragma unroll
    for (int j = 0; j < 4; j++) {
        L[j] = M[j + 1];
        bool bnd = false;
        if (L[j] > 0) {
            bool allfg = (U[j] > 0) & (U[j+1] > 0) & (U[j+2] > 0)
                       & (M[j] > 0) & (M[j+2] > 0)
                       & (D[j] > 0) & (D[j+1] > 0) & (D[j+2] > 0);
            bnd = !allfg;
        }
        isb[j] = bnd;
        gsv[j] = bnd ? (set * NSLOT + L[j]) : zs;
    }
    // cache slot ids (aligned int4)
    {
        long long i = base + ((long long)r << 9) + c0;
        *(int4*)(g_lab1 + i) = make_int4(gsv[0], gsv[1], gsv[2], gsv[3]);
    }

    // zero-slot (non-boundary) contributions, block-reduced
    unsigned zc = 0, zl = 0;
    #pragma unroll
    for (int j = 0; j < 4; j++)
        if (!isb[j]) { zc++; zl += (unsigned)(c0 + j); }
    unsigned zr = zc * (unsigned)r;
    for (int o = 16; o > 0; o >>= 1) {
        zc += __shfl_down_sync(0xffffffffu, zc, o);
        zr += __shfl_down_sync(0xffffffffu, zr, o);
        zl += __shfl_down_sync(0xffffffffu, zl, o);
    }
    __shared__ unsigned sc[8], sr[8], sl[8];
    int wid = threadIdx.y;
    if (tx == 0) { sc[wid] = zc; sr[wid] = zr; sl[wid] = zl; }
    __syncthreads();
    if (tx == 0 && wid == 0) {
        unsigned tc = 0, tr = 0, tl = 0;
        for (int i = 0; i < 8; i++) { tc += sc[i]; tr += sr[i]; tl += sl[i]; }
        if (tc) {
            atomicAdd(&g_cnt[zs],  (int)tc);
            atomicAdd(&g_sumR[zs], (int)tr);
            atomicAdd(&g_sumC[zs], (int)tl);
        }
    }
    // boundary pixels: direct atomics (sparse)
    #pragma unroll
    for (int j = 0; j < 4; j++) {
        if (isb[j]) {
            atomicAdd(&g_cnt[gsv[j]], 1);
            atomicAdd(&g_sumR[gsv[j]], r);
            atomicAdd(&g_sumC[gsv[j]], c0 + j);
        }
    }
}

// ---------------- centroid precompute + lazy init of min fields ----------------
__global__ void k_cent()
{
    long long i = (long long)blockIdx.x * blockDim.x + threadIdx.x;
    long long stride = (long long)gridDim.x * blockDim.x;
    for (long long j = i; j < TOTSLOT; j += stride) {
        int n = g_cnt[j];
        if (n > 0) {
            g_cent[j][0] = (double)g_sumR[j] / (double)n;
            g_cent[j][1] = (double)g_sumC[j] / (double)n;
            g_min32[j] = ~0u;
            g_minKey[j] = ~0ull;
            g_minRC[j] = ~0u;
        }
    }
}

// ---------------- pass A: fp32 prefilter min angle per slot ----------------
__global__ void k_angA()
{
    int sb = blockIdx.z; int set = sb >> 3, b = sb & 7;
    int c = blockIdx.x * 32 + threadIdx.x;
    int r = blockIdx.y * 8  + threadIdx.y;
    int i = (sb << 18) | (r << 9) | c;
    int gs = g_lab1[i];
    int zs = set * NSLOT + b * SLOTS_PER_IMG;
    bool isb = (gs != zs);

    double cr = g_cent[gs][0], cc = g_cent[gs][1];
    float ang = atan2f((float)((double)c - cc), (float)((double)r - cr));
    unsigned key = key32_of(ang);

    if (isb) atomicMin(&g_min32[gs], key);

    unsigned zkey = isb ? ~0u : key;
    for (int o = 16; o > 0; o >>= 1) {
        unsigned v = __shfl_down_sync(0xffffffffu, zkey, o);
        zkey = min(zkey, v);
    }
    __shared__ unsigned sk[8];
    int wid = threadIdx.y, lane = threadIdx.x;
    if (lane == 0) sk[wid] = zkey;
    __syncthreads();
    if (lane == 0 && wid == 0) {
        unsigned mk = sk[0];
        for (int i2 = 1; i2 < 8; i2++) mk = min(mk, sk[i2]);
        if (mk != ~0u) atomicMin(&g_min32[zs], mk);
    }
}

// ---------------- pass B: exact fp64 min among fp32-filtered candidates ----------------
__global__ void k_angB()
{
    int sb = blockIdx.z;
    int c = blockIdx.x * 32 + threadIdx.x;
    int r = blockIdx.y * 8  + threadIdx.y;
    int i = (sb << 18) | (r << 9) | c;
    int gs = g_lab1[i];

    double cr = g_cent[gs][0], cc = g_cent[gs][1];
    double dy = (double)c - cc, dx = (double)r - cr;
    float ang = atan2f((float)dy, (float)dx);
    float amin = ang_of_key32(g_min32[gs]);
    if (ang <= amin + ANG_EPS) {
        unsigned long long key = angle_key(dy, dx);
        atomicMin(&g_minKey[gs], key);
    }
}

// ---------------- pass C: raster tie-break among exact-min pixels ----------------
__global__ void k_angC()
{
    int sb = blockIdx.z;
    int c = blockIdx.x * 32 + threadIdx.x;
    int r = blockIdx.y * 8  + threadIdx.y;
    int i = (sb << 18) | (r << 9) | c;
    int gs = g_lab1[i];

    double cr = g_cent[gs][0], cc = g_cent[gs][1];
    double dy = (double)c - cc, dx = (double)r - cr;
    float ang = atan2f((float)dy, (float)dx);
    float amin = ang_of_key32(g_min32[gs]);
    if (ang <= amin + ANG_EPS) {
        unsigned long long key = angle_key(dy, dx);
        if (key == g_minKey[gs]) {
            unsigned rc = ((unsigned)r << 9) | (unsigned)c;
            atomicMin(&g_minRC[gs], rc);
        }
    }
}

// ---------------- finalize: ordered compaction ----------------
__global__ void k_final()
{
    int sb = blockIdx.x; int set = sb >> 3, b = sb & 7;
    int base = set * NSLOT + b * SLOTS_PER_IMG;
    const int CH = (SLOTS_PER_IMG + 1023) / 1024;
    int t = threadIdx.x;
    int lo = t * CH, hi = min(lo + CH, SLOTS_PER_IMG);

    int act = 0, kept = 0;
    for (int l = lo; l < hi; l++) {
        int n = g_cnt[base + l];
        if (n > 0) { act++; if (n >= 10) kept++; }
    }
    __shared__ int sKept[1024];
    __shared__ int offs[1025];
    __shared__ int sAct[1024];
    __shared__ int totAct;
    sAct[t] = act; sKept[t] = kept;
    __syncthreads();
    if (t == 0) {
        int s = 0, a = 0;
        for (int i = 0; i < 1024; i++) { offs[i] = s; s += sKept[i]; a += sAct[i]; }
        offs[1024] = s; totAct = a;
    }
    __syncthreads();

    int pos = offs[t];
    for (int l = lo; l < hi; l++) {
        int n = g_cnt[base + l];
        if (n >= 10) {
            if (pos < DMAX) {
                unsigned rc = g_minRC[base + l];
                double r0 = (double)(rc >> 9), c0 = (double)(rc & 511u);
                double Ab = sqrt(r0 * r0 + c0 * c0);
                g_desc[sb][pos][0] = (double)g_sumR[base + l] / (double)n;
                g_desc[sb][pos][1] = (double)g_sumC[base + l] / (double)n;
                g_desc[sb][pos][2] = Ab / PI_D;
                g_desc[sb][pos][3] = Ab / (2.0 * PI_D);
            }
            pos++;
        }
    }
    if (t == 0) {
        int tot = offs[1024]; if (tot > DMAX) tot = DMAX;
        g_M[sb] = tot;
        g_valid[sb] = (totAct > 1) && (tot > 0);
    }
}

// ---------------- matching + output ----------------
__global__ void k_match(const float* __restrict__ wptr, float* __restrict__ out)
{
    __shared__ double red[256];
    __shared__ double Stot;
    int t = threadIdx.x;
    if (t == 0) Stot = 0.0;
    __syncthreads();

    for (int b = 0; b < 8; b++) {
        double local = 0.0;
        if (g_valid[b] && g_valid[8 + b]) {
            int Mp = g_M[b], Mt = g_M[8 + b];
            const double (*P)[4] = g_desc[b];
            const double (*T)[4] = g_desc[8 + b];
            if (Mt <= Mp) {
                for (int i = t; i < Mt; i += 256) {
                    double tx = T[i][0], ty = T[i][1];
                    int m = 0; double bd = 1e300;
                    for (int j = 0; j < Mp; j++) {
                        double dx = tx - P[j][0], dy = ty - P[j][1];
                        double d = dx * dx + dy * dy;
                        if (d < bd) { bd = d; m = j; }
                    }
                    local += fabs(P[m][2] - T[i][2]) + fabs(P[m][3] - T[i][3]);
                }
            } else {
                for (int i = t; i < Mp; i += 256) {
                    double px = P[i][0], py = P[i][1];
                    int m = 0; double bd = 1e300;
                    for (int j = 0; j < Mt; j++) {
                        double dx = px - T[j][0], dy = py - T[j][1];
                        double d = dx * dx + dy * dy;
                        if (d < bd) { bd = d; m = j; }
                    }
                    local += fabs(T[m][2] - P[i][2]) + fabs(T[m][3] - P[i][3]);
                }
            }
        }
        red[t] = local; __syncthreads();
        for (int s = 128; s > 0; s >>= 1) { if (t < s) red[t] += red[t + s]; __syncthreads(); }
        if (t == 0) Stot += red[0];
        __syncthreads();
    }
    if (t == 0) {
        float w = *wptr;
        out[0] = (float)Stot * (0.5f * w * w);
    }
}

// ---------------- launch ----------------
extern "C" void kernel_launch(void* const* d_in, const int* in_sizes, int n_in,
                              void* d_out, int out_size)
{
    (void)in_sizes; (void)n_in; (void)out_size;
    const float* pred = (const float*)d_in[0];
    const float* tgt  = (const float*)d_in[1];
    const float* w    = (const float*)d_in[2];
    float* out = (float*)d_out;

    static bool attr_set = false;
    if (!attr_set) {
        cudaFuncSetAttribute(k_cc, cudaFuncAttributeMaxDynamicSharedMemorySize, CC_SMEM);
        attr_set = true;
    }

    k_init<<<4096, 256>>>();
    k_fill<<<NPIX / 256, 256>>>(pred, tgt);

    // 500 iterations = 31 launches of 16 + 1 launch of 4 (both even)
    for (int k = 0; k < 32; k++) {
        int iters = (k == 31) ? 4 : 16;
        k_cc<<<dim3(4, 4, 16), CC_TPB, CC_SMEM>>>(k & 1, iters);
    }
    // 32 launches (even) -> final labels in g_lab0

    dim3 bl(32, 8);
    k_stats<<<dim3(4, 64, 16), bl>>>();   // 4 px/thread in x
    k_cent <<<4096, 256>>>();
    k_angA <<<dim3(16, 64, 16), bl>>>();
    k_angB <<<dim3(16, 64, 16), bl>>>();
    k_angC <<<dim3(16, 64, 16), bl>>>();
    k_final<<<16, 1024>>>();
    k_match<<<1, 256>>>(w, out);
}